// round 16
// baseline (speedup 1.0000x reference)
#include <cuda_runtime.h>
#include <cuda_fp16.h>
#include <math.h>
#include <stdint.h>

#define BATCH 4
#define TT    2048
#define DD    1024
#define HALF_D 512

// Scratch (allocation-free rule: __device__ globals).
// g_Q/K/V used as __half (first 16MB). g_S over time:
//   [0 .. 8M floats)  = Sh (16M halfs): scores -> probs
//   [8M .. 12M)       = xh (8M halfs)        } dead once scores run
//   [12M .. 13.5M)    = wqh/wkh/wvh          }
__device__ float g_Q[(size_t)BATCH * TT * DD];   // 32 MB
__device__ float g_K[(size_t)BATCH * TT * DD];   // 32 MB
__device__ float g_V[(size_t)BATCH * TT * DD];   // 32 MB
__device__ float g_S[(size_t)BATCH * TT * TT];   // 64 MB
__device__ float g_cosT[(size_t)HALF_D * TT];    // 4 MB, layout [pair][t]
__device__ float g_sinT[(size_t)HALF_D * TT];    // 4 MB

// ---------------------------------------------------------------------------
// helpers
// ---------------------------------------------------------------------------
__device__ __forceinline__ void cp16(uint32_t dst, const void* src) {
    asm volatile("cp.async.cg.shared.global [%0], [%1], 16;" :: "r"(dst), "l"(src));
}
__device__ __forceinline__ void cp_commit() { asm volatile("cp.async.commit_group;"); }
__device__ __forceinline__ void cp_wait1()  { asm volatile("cp.async.wait_group 1;"); }

__device__ __forceinline__ uint32_t smem_u32(const void* p) {
    return (uint32_t)__cvta_generic_to_shared(p);
}
__device__ __forceinline__ void ldsm_x4(uint32_t* f, uint32_t addr) {
    asm volatile("ldmatrix.sync.aligned.m8n8.x4.shared.b16 {%0,%1,%2,%3}, [%4];"
                 : "=r"(f[0]), "=r"(f[1]), "=r"(f[2]), "=r"(f[3]) : "r"(addr));
}
__device__ __forceinline__ void ldsm_x4_t(uint32_t* f, uint32_t addr) {
    asm volatile("ldmatrix.sync.aligned.m8n8.x4.trans.shared.b16 {%0,%1,%2,%3}, [%4];"
                 : "=r"(f[0]), "=r"(f[1]), "=r"(f[2]), "=r"(f[3]) : "r"(addr));
}
// fp16 MMA, fp32 accumulate: m16n8k16
__device__ __forceinline__ void mma_f16(float c[4], const uint32_t a[4],
                                        const uint32_t b[2]) {
    asm volatile(
        "mma.sync.aligned.m16n8k16.row.col.f32.f16.f16.f32 "
        "{%0,%1,%2,%3},{%4,%5,%6,%7},{%8,%9},{%0,%1,%2,%3};"
        : "+f"(c[0]), "+f"(c[1]), "+f"(c[2]), "+f"(c[3])
        : "r"(a[0]), "r"(a[1]), "r"(a[2]), "r"(a[3]), "r"(b[0]), "r"(b[1]));
}

// FFMA-only exp (v <= 0): e^v = 2^(v*log2e); no MUFU.
__device__ __forceinline__ float fexp(float v) {
    float y = fmaxf(v * 1.4426950408889634f, -120.f);
    float r = rintf(y);
    float fl = (y - r) * 0.6931471805599453f;
    float p = 1.3888888888888889e-3f;
    p = fmaf(p, fl, 8.3333333333333333e-3f);
    p = fmaf(p, fl, 4.1666666666666664e-2f);
    p = fmaf(p, fl, 1.6666666666666666e-1f);
    p = fmaf(p, fl, 5.0e-1f);
    p = fmaf(p, fl, 1.0f);
    p = fmaf(p, fl, 1.0f);
    return __int_as_float(((int)r + 127) << 23) * p;
}

// ---------------------------------------------------------------------------
// Fused setup: fp16-round x/Wq/Wk/Wv + RoPE cos/sin table [pair][t].
// ---------------------------------------------------------------------------
__global__ __launch_bounds__(256) void setup_kernel(
    const float4* __restrict__ x,
    const float4* __restrict__ Wq, const float4* __restrict__ Wk,
    const float4* __restrict__ Wv,
    __half2* __restrict__ xh,
    __half2* __restrict__ wqh, __half2* __restrict__ wkh, __half2* __restrict__ wvh,
    float* __restrict__ cosT, float* __restrict__ sinT)
{
    int b = blockIdx.x, tid = threadIdx.x;
    if (b < 5632) {
        const float4* s; __half2* d; int i8;
        if (b < 4096) { s = x; d = xh; i8 = b * 256 + tid; }
        else {
            int wi = b - 4096;
            int w = wi >> 9, o = wi & 511;
            s = (w == 0) ? Wq : ((w == 1) ? Wk : Wv);
            d = (w == 0) ? wqh : ((w == 1) ? wkh : wvh);
            i8 = o * 256 + tid;
        }
        float4 a = s[i8 * 2], c = s[i8 * 2 + 1];
        d[i8 * 4 + 0] = __floats2half2_rn(a.x, a.y);
        d[i8 * 4 + 1] = __floats2half2_rn(a.z, a.w);
        d[i8 * 4 + 2] = __floats2half2_rn(c.x, c.y);
        d[i8 * 4 + 3] = __floats2half2_rn(c.z, c.w);
    } else {
        int idx = (b - 5632) * 256 + tid;         // < HALF_D*TT
        int pair = idx >> 11;                      // constant within block
        __shared__ double sh_theta;
        if (tid == 0)
            sh_theta = exp(-2.0 * (double)pair / (double)DD * 9.210340371976184);
        __syncthreads();
        float theta = (float)sh_theta;
        int t = idx & (TT - 1);
        float ang = (float)t * theta;              // fp32, matches reference
        double xx = (double)ang;
        double k = floor(xx * 0.15915494309189535);
        float r = (float)(xx - k * 6.283185307179586);
        cosT[idx] = cosf(r);
        sinT[idx] = sinf(r);
    }
}

// ---------------------------------------------------------------------------
// FP16 MMA GEMM, NT: C[M,N] = A[M,K]*B[N,K]^T (both K-contiguous halfs).
// 128x128 tile, BK=64 halfs, 3-stage cp.async, occ=2 (R14 structure).
// B-frags via paired ldmatrix.x4; next-tile prefetch issued at loop head.
// qkv mode: z selects W/out; rope fused for z<2; outputs __half.
// scores mode (qkv=0): z=batch, causal block skip, __half output.
// ---------------------------------------------------------------------------
__global__ __launch_bounds__(256, 2) void mma_nt(
    const __half* __restrict__ A,
    const __half* __restrict__ B0, const __half* __restrict__ B1,
    const __half* __restrict__ B2,
    __half* __restrict__ C0, __half* __restrict__ C1, __half* __restrict__ C2,
    int K, int lda, int ldb, int ldc,
    long long sA, long long sB, long long sC,
    int qkv,
    const float* __restrict__ cosT, const float* __restrict__ sinT)
{
    int bz = blockIdx.z;
    const __half* Ap = A;
    const __half* Bp; __half* Cp; int rope;
    if (qkv) {
        Bp = (bz == 0) ? B0 : ((bz == 1) ? B1 : B2);
        Cp = (bz == 0) ? C0 : ((bz == 1) ? C1 : C2);
        rope = (bz < 2) ? 1 : 0;
    } else {
        if ((int)blockIdx.x > (int)blockIdx.y + 1) return;
        Ap = A  + (long long)bz * sA;
        Bp = B0 + (long long)bz * sB;
        Cp = C0 + (long long)bz * sC;
        rope = 0;
    }
    const __half* Ab = Ap + (long long)blockIdx.y * 128 * lda;
    const __half* Bb = Bp + (long long)blockIdx.x * 128 * ldb;

    extern __shared__ char sm[];
    uint32_t su = smem_u32(sm);

    int tid = threadIdx.x, lane = tid & 31, warp = tid >> 5;
    int wy = warp >> 2, wx = warp & 3;
    int grp = lane >> 2, l4 = lane & 3;
    int arow_l = lane & 15, ak_h = lane >> 4;
    int b_row8 = lane & 7, b_ksel = (lane >> 3) & 1, b_nsel = (lane >> 4) & 1;

    float acc[4][4][4];
#pragma unroll
    for (int mt = 0; mt < 4; mt++)
#pragma unroll
        for (int nt = 0; nt < 4; nt++)
#pragma unroll
            for (int j = 0; j < 4; j++) acc[mt][nt][j] = 0.f;

    int ntiles = K >> 6;   // BK=64 halfs

    // stage: A 128x128B (16KB) + B 128x128B (16KB) = 32KB; 3 stages
#define NT_LOAD(stage, k0)                                                    \
    {                                                                         \
        uint32_t sa_ = su + (stage) * 32768;                                  \
        _Pragma("unroll")                                                     \
        for (int l = 0; l < 4; l++) {                                         \
            int v = tid + l * 256;                                            \
            int r = v >> 3, c4 = v & 7;                                       \
            uint32_t off = (uint32_t)(r * 128 + ((c4 ^ (r & 7)) << 4));       \
            cp16(sa_ + off,         Ab + (long long)r * lda + (k0) + c4 * 8); \
            cp16(sa_ + 16384 + off, Bb + (long long)r * ldb + (k0) + c4 * 8); \
        }                                                                     \
    }

    NT_LOAD(0, 0);  cp_commit();
    NT_LOAD(1, 64); cp_commit();

    int rs = 0;
    for (int t = 0; t < ntiles; t++) {
        cp_wait1();
        __syncthreads();
        // issue next-tile prefetch FIRST so it overlaps this tile's MMAs
        {
            int tn = t + 2;
            if (tn < ntiles) {
                int ws = rs + 2; if (ws >= 3) ws -= 3;
                NT_LOAD(ws, tn * 64);
            }
            cp_commit();
        }
        uint32_t sa = su + rs * 32768;
        uint32_t sb = sa + 16384;
#pragma unroll
        for (int ks = 0; ks < 4; ks++) {       // k16 per step
            int kc = ks * 2;                   // 16B chunk index
            uint32_t afr[4][4], bfr[4][2];
#pragma unroll
            for (int mt = 0; mt < 4; mt++) {
                int row = wy * 64 + mt * 16 + arow_l;
                int ch  = (kc + ak_h) ^ (row & 7);
                ldsm_x4(afr[mt], sa + (uint32_t)(row * 128 + (ch << 4)));
            }
#pragma unroll
            for (int ntp = 0; ntp < 4; ntp += 2) {  // paired: 2x ldsm_x4
                int row = wx * 32 + (ntp + b_nsel) * 8 + b_row8;
                int ch  = (kc + b_ksel) ^ (row & 7);
                ldsm_x4(&bfr[ntp][0], sb + (uint32_t)(row * 128 + (ch << 4)));
            }
#pragma unroll
            for (int mt = 0; mt < 4; mt++)
#pragma unroll
                for (int nt = 0; nt < 4; nt++)
                    mma_f16(acc[mt][nt], afr[mt], bfr[nt]);
        }
        rs++; if (rs == 3) rs = 0;
    }
#undef NT_LOAD

    int row0 = blockIdx.y * 128 + wy * 64;
    int col0 = blockIdx.x * 128 + wx * 32;
#pragma unroll
    for (int mt = 0; mt < 4; mt++) {
        int r1 = row0 + mt * 16 + grp;
        int r2 = r1 + 8;
#pragma unroll
        for (int nt = 0; nt < 4; nt++) {
            int cc = col0 + nt * 8 + l4 * 2;
            float e0 = acc[mt][nt][0], o0 = acc[mt][nt][1];
            float e1 = acc[mt][nt][2], o1 = acc[mt][nt][3];
            if (rope) {
                int p  = cc >> 1;
                int t1 = r1 & (TT - 1), t2 = r2 & (TT - 1);
                float c1v = cosT[(size_t)p * TT + t1], s1v = sinT[(size_t)p * TT + t1];
                float c2v = cosT[(size_t)p * TT + t2], s2v = sinT[(size_t)p * TT + t2];
                float ne0 = e0 * c1v - o0 * s1v, no0 = e0 * s1v + o0 * c1v;
                float ne1 = e1 * c2v - o1 * s2v, no1 = e1 * s2v + o1 * c2v;
                e0 = ne0; o0 = no0; e1 = ne1; o1 = no1;
            }
            *(__half2*)(Cp + (long long)r1 * ldc + cc) = __floats2half2_rn(e0, o0);
            *(__half2*)(Cp + (long long)r2 * ldc + cc) = __floats2half2_rn(e1, o1);
        }
    }
}

// ---------------------------------------------------------------------------
// FP16 MMA GEMM, NN: C[M,N] = A[M,K]*B[K,N], fp32 output.
// A (P) K-contiguous; B (V) N-contiguous — B frags via paired ldmatrix.x4
// .trans on a [k][136]-half tile (272B rows). K bounded per q-block.
// 3-stage pipe, occ=2 (R14 structure), prefetch issued at loop head.
// ---------------------------------------------------------------------------
__global__ __launch_bounds__(256, 2) void mma_nn(
    const __half* __restrict__ A, const __half* __restrict__ B,
    float* __restrict__ C,
    int K, int lda, int ldb, int ldc,
    long long sA, long long sB, long long sC)
{
    const __half* Ab = A + (long long)blockIdx.z * sA + (long long)blockIdx.y * 128 * lda;
    const __half* Bb = B + (long long)blockIdx.z * sB + (long long)blockIdx.x * 128;
    float*        Cb = C + (long long)blockIdx.z * sC;

    int Kend = min(((int)blockIdx.y + 2) * 128, K);
    int ntiles = Kend >> 6;

    extern __shared__ char sm[];
    uint32_t su = smem_u32(sm);

    int tid = threadIdx.x, lane = tid & 31, warp = tid >> 5;
    int wy = warp >> 2, wx = warp & 3;
    int grp = lane >> 2, l4 = lane & 3;
    int arow_l = lane & 15, ak_h = lane >> 4;
    int lan16 = lane & 15, n8sel = ((lane >> 4) & 1) * 8;

    float acc[4][4][4];
#pragma unroll
    for (int mt = 0; mt < 4; mt++)
#pragma unroll
        for (int nt = 0; nt < 4; nt++)
#pragma unroll
            for (int j = 0; j < 4; j++) acc[mt][nt][j] = 0.f;

    // stage: A 16384B + B 64*272B = 17408B -> 33792B; 3 stages
#define NN_LOAD(stage, k0)                                                      \
    {                                                                           \
        uint32_t sa_ = su + (stage) * 33792;                                    \
        _Pragma("unroll")                                                       \
        for (int l = 0; l < 4; l++) {                                           \
            int v = tid + l * 256;                                              \
            int r = v >> 3, c4 = v & 7;                                         \
            uint32_t off = (uint32_t)(r * 128 + ((c4 ^ (r & 7)) << 4));         \
            cp16(sa_ + off, Ab + (long long)r * lda + (k0) + c4 * 8);           \
            int br = v >> 4, bc = (v & 15) * 8;                                 \
            cp16(sa_ + 16384 + (uint32_t)(br * 272 + bc * 2),                   \
                 Bb + (long long)((k0) + br) * ldb + bc);                       \
        }                                                                       \
    }

    NN_LOAD(0, 0);  cp_commit();
    NN_LOAD(1, 64); cp_commit();

    int rs = 0;
    for (int t = 0; t < ntiles; t++) {
        cp_wait1();
        __syncthreads();
        {
            int tn = t + 2;
            if (tn < ntiles) {
                int ws = rs + 2; if (ws >= 3) ws -= 3;
                NN_LOAD(ws, tn * 64);
            }
            cp_commit();
        }
        uint32_t sa = su + rs * 33792;
        uint32_t sb = sa + 16384;
#pragma unroll
        for (int ks = 0; ks < 4; ks++) {
            int kc = ks * 2;
            int kb = ks * 16;                  // k offset in halfs
            uint32_t afr[4][4], bfr[4][2];
#pragma unroll
            for (int mt = 0; mt < 4; mt++) {
                int row = wy * 64 + mt * 16 + arow_l;
                int ch  = (kc + ak_h) ^ (row & 7);
                ldsm_x4(afr[mt], sa + (uint32_t)(row * 128 + (ch << 4)));
            }
#pragma unroll
            for (int ntp = 0; ntp < 4; ntp += 2) {  // paired: 2x ldsm_x4_t
                int n0 = wx * 32 + ntp * 8 + n8sel;
                ldsm_x4_t(&bfr[ntp][0],
                          sb + (uint32_t)((kb + lan16) * 272 + n0 * 2));
            }
#pragma unroll
            for (int mt = 0; mt < 4; mt++)
#pragma unroll
                for (int nt = 0; nt < 4; nt++)
                    mma_f16(acc[mt][nt], afr[mt], bfr[nt]);
        }
        rs++; if (rs == 3) rs = 0;
    }
#undef NN_LOAD

    int row0 = blockIdx.y * 128 + wy * 64;
    int col0 = blockIdx.x * 128 + wx * 32;
#pragma unroll
    for (int mt = 0; mt < 4; mt++) {
        int r1 = row0 + mt * 16 + grp;
        int r2 = r1 + 8;
#pragma unroll
        for (int nt = 0; nt < 4; nt++) {
            int cc = col0 + nt * 8 + l4 * 2;
            *(float2*)(Cb + (long long)r1 * ldc + cc) =
                make_float2(acc[mt][nt][0], acc[mt][nt][1]);
            *(float2*)(Cb + (long long)r2 * ldc + cc) =
                make_float2(acc[mt][nt][2], acc[mt][nt][3]);
        }
    }
}

// ---------------------------------------------------------------------------
// Row softmax on __half scores. 8 halfs/thread covers a 2048 row.
// Valid prefix n=q+2, scale 1/32, fp32 math, fp16 probs. Zero-fill to bound.
// ---------------------------------------------------------------------------
__global__ __launch_bounds__(256) void softmax_rows(__half* __restrict__ S)
{
    int row = blockIdx.x;                 // b*T + q
    int q   = row & (TT - 1);
    __half* s = S + (size_t)row * TT;
    int n    = min(q + 2, TT);
    int zend = min((((q >> 7) + 2) << 7), TT);
    int nv8  = (n + 7) >> 3;

    int tid = threadIdx.x;
    uint4* s8 = (uint4*)s;

    float v[8];
    float m = -1e30f;
    if (tid < nv8) {
        uint4 u = s8[tid];
        __half2* h = (__half2*)&u;
        int base = tid * 8;
#pragma unroll
        for (int k = 0; k < 4; k++) {
            float2 f = __half22float2(h[k]);
            v[k*2]   = (base + k*2     < n) ? f.x : -1e30f;
            v[k*2+1] = (base + k*2 + 1 < n) ? f.y : -1e30f;
        }
#pragma unroll
        for (int k = 0; k < 8; k++) m = fmaxf(m, v[k]);
    } else {
#pragma unroll
        for (int k = 0; k < 8; k++) v[k] = -1e30f;
    }

    __shared__ float red[8];
#pragma unroll
    for (int o = 16; o; o >>= 1) m = fmaxf(m, __shfl_xor_sync(0xffffffffu, m, o));
    if ((tid & 31) == 0) red[tid >> 5] = m;
    __syncthreads();
    m = red[0];
#pragma unroll
    for (int w = 1; w < 8; w++) m = fmaxf(m, red[w]);
    __syncthreads();

    float sum = 0.f;
#pragma unroll
    for (int k = 0; k < 8; k++) {
        v[k] = fexp((v[k] - m) * 0.03125f);
        sum += v[k];
    }
    if (tid >= nv8) sum = 0.f;
#pragma unroll
    for (int o = 16; o; o >>= 1) sum += __shfl_xor_sync(0xffffffffu, sum, o);
    if ((tid & 31) == 0) red[tid >> 5] = sum;
    __syncthreads();
    float tot = 0.f;
#pragma unroll
    for (int w = 0; w < 8; w++) tot += red[w];
    float inv = 1.0f / tot;

    if (tid < nv8) {
        uint4 u;
        __half2* h = (__half2*)&u;
#pragma unroll
        for (int k = 0; k < 4; k++)
            h[k] = __floats2half2_rn(v[k*2] * inv, v[k*2+1] * inv);
        s8[tid] = u;
    }
    for (int j = nv8 * 8 + tid; j < zend; j += 256) s[j] = __ushort_as_half(0);
}

// ---------------------------------------------------------------------------
// Launch: setup -> fused QKV (rope) -> scores -> softmax -> PV
// ---------------------------------------------------------------------------
extern "C" void kernel_launch(void* const* d_in, const int* in_sizes, int n_in,
                              void* d_out, int out_size)
{
    const float* x  = (const float*)d_in[0];
    const float* Wq = (const float*)d_in[1];
    const float* Wk = (const float*)d_in[2];
    const float* Wv = (const float*)d_in[3];
    float* out = (float*)d_out;

    float *Qf, *Kf, *Vf, *S, *cT, *sT;
    cudaGetSymbolAddress((void**)&Qf, g_Q);
    cudaGetSymbolAddress((void**)&Kf, g_K);
    cudaGetSymbolAddress((void**)&Vf, g_V);
    cudaGetSymbolAddress((void**)&S,  g_S);
    cudaGetSymbolAddress((void**)&cT, g_cosT);
    cudaGetSymbolAddress((void**)&sT, g_sinT);

    __half* Qh = (__half*)Qf;
    __half* Kh = (__half*)Kf;
    __half* Vh = (__half*)Vf;
    __half* Sh = (__half*)S;                                  // 16M halfs
    __half* xh  = (__half*)(S + (size_t)8  * 1024 * 1024);    // 8M halfs
    __half* wqh = (__half*)(S + (size_t)12 * 1024 * 1024);    // 1M halfs each
    __half* wkh = wqh + 1024 * 1024;
    __half* wvh = wkh + 1024 * 1024;

    cudaFuncSetAttribute(mma_nt, cudaFuncAttributeMaxDynamicSharedMemorySize, 98304);
    cudaFuncSetAttribute(mma_nn, cudaFuncAttributeMaxDynamicSharedMemorySize, 101376);

    dim3 blk(256);
    const long long TD  = (long long)TT * DD;   // in halfs
    const long long TT2 = (long long)TT * TT;

    // Setup: fp16-round x/W* (5632 blocks) + rope table (4096 blocks)
    setup_kernel<<<5632 + 4096, blk>>>(
        (const float4*)x, (const float4*)Wq, (const float4*)Wk, (const float4*)Wv,
        (__half2*)xh, (__half2*)wqh, (__half2*)wkh, (__half2*)wvh, cT, sT);

    // Fused QKV: z=0/1/2 -> Q/K/V (half); rope fused for Q,K
    mma_nt<<<dim3(DD / 128, (BATCH * TT) / 128, 3), blk, 98304>>>(
        xh, wqh, wkh, wvh, Qh, Kh, Vh,
        DD, DD, DD, DD, 0, 0, 0, 1, cT, sT);

    // Scores: Sh[b] = Qr[b]*Kr[b]^T (half out; causal block skip)
    mma_nt<<<dim3(TT / 128, TT / 128, BATCH), blk, 98304>>>(
        Qh, Kh, nullptr, nullptr, Sh, nullptr, nullptr,
        DD, DD, DD, TT, TD, TD, TT2, 0, cT, sT);

    // Softmax (scale 1/32, causal mask, fp16 probs, zero-fill)
    softmax_rows<<<BATCH * TT, blk>>>(Sh);

    // Out: O[b] = P[b]*V[b] (K bounded per q-block; fp32 out)
    mma_nn<<<dim3(DD / 128, TT / 128, BATCH), blk, 101376>>>(
        Sh, Vh, out, TT, TT, DD, DD, TT2, TD, TD);
}

// round 17
// speedup vs baseline: 1.5710x; 1.5710x over previous
#include <cuda_runtime.h>
#include <cuda_fp16.h>
#include <math.h>
#include <stdint.h>

#define BATCH 4
#define TT    2048
#define DD    1024
#define HALF_D 512

// Scratch (allocation-free rule: __device__ globals).
// g_Q/K/V used as __half (first 16MB). g_S over time:
//   [0 .. 8M floats)  = Sh (16M halfs): scores -> probs
//   [8M .. 12M)       = xh (8M halfs)        } dead once scores run
//   [12M .. 13.5M)    = wqh/wkh/wvh          }
__device__ float g_Q[(size_t)BATCH * TT * DD];   // 32 MB
__device__ float g_K[(size_t)BATCH * TT * DD];   // 32 MB
__device__ float g_V[(size_t)BATCH * TT * DD];   // 32 MB
__device__ float g_S[(size_t)BATCH * TT * TT];   // 64 MB
__device__ float g_cosT[(size_t)HALF_D * TT];    // 4 MB, layout [pair][t]
__device__ float g_sinT[(size_t)HALF_D * TT];    // 4 MB

// ---------------------------------------------------------------------------
// helpers
// ---------------------------------------------------------------------------
__device__ __forceinline__ void cp16(uint32_t dst, const void* src) {
    asm volatile("cp.async.cg.shared.global [%0], [%1], 16;" :: "r"(dst), "l"(src));
}
__device__ __forceinline__ void cp_commit() { asm volatile("cp.async.commit_group;"); }
__device__ __forceinline__ void cp_wait1()  { asm volatile("cp.async.wait_group 1;"); }

__device__ __forceinline__ uint32_t smem_u32(const void* p) {
    return (uint32_t)__cvta_generic_to_shared(p);
}
__device__ __forceinline__ void ldsm_x4(uint32_t f[4], uint32_t addr) {
    asm volatile("ldmatrix.sync.aligned.m8n8.x4.shared.b16 {%0,%1,%2,%3}, [%4];"
                 : "=r"(f[0]), "=r"(f[1]), "=r"(f[2]), "=r"(f[3]) : "r"(addr));
}
__device__ __forceinline__ void ldsm_x2(uint32_t f[2], uint32_t addr) {
    asm volatile("ldmatrix.sync.aligned.m8n8.x2.shared.b16 {%0,%1}, [%2];"
                 : "=r"(f[0]), "=r"(f[1]) : "r"(addr));
}
__device__ __forceinline__ void ldsm_x2_t(uint32_t f[2], uint32_t addr) {
    asm volatile("ldmatrix.sync.aligned.m8n8.x2.trans.shared.b16 {%0,%1}, [%2];"
                 : "=r"(f[0]), "=r"(f[1]) : "r"(addr));
}
// fp16 MMA, fp32 accumulate: m16n8k16
__device__ __forceinline__ void mma_f16(float c[4], const uint32_t a[4],
                                        const uint32_t b[2]) {
    asm volatile(
        "mma.sync.aligned.m16n8k16.row.col.f32.f16.f16.f32 "
        "{%0,%1,%2,%3},{%4,%5,%6,%7},{%8,%9},{%0,%1,%2,%3};"
        : "+f"(c[0]), "+f"(c[1]), "+f"(c[2]), "+f"(c[3])
        : "r"(a[0]), "r"(a[1]), "r"(a[2]), "r"(a[3]), "r"(b[0]), "r"(b[1]));
}

// FFMA-only exp (v <= 0): e^v = 2^(v*log2e); no MUFU.
__device__ __forceinline__ float fexp(float v) {
    float y = fmaxf(v * 1.4426950408889634f, -120.f);
    float r = rintf(y);
    float fl = (y - r) * 0.6931471805599453f;
    float p = 1.3888888888888889e-3f;
    p = fmaf(p, fl, 8.3333333333333333e-3f);
    p = fmaf(p, fl, 4.1666666666666664e-2f);
    p = fmaf(p, fl, 1.6666666666666666e-1f);
    p = fmaf(p, fl, 5.0e-1f);
    p = fmaf(p, fl, 1.0f);
    p = fmaf(p, fl, 1.0f);
    return __int_as_float(((int)r + 127) << 23) * p;
}

// ---------------------------------------------------------------------------
// Fused setup: fp16-round x/Wq/Wk/Wv + RoPE cos/sin table [pair][t].
// ---------------------------------------------------------------------------
__global__ __launch_bounds__(256) void setup_kernel(
    const float4* __restrict__ x,
    const float4* __restrict__ Wq, const float4* __restrict__ Wk,
    const float4* __restrict__ Wv,
    __half2* __restrict__ xh,
    __half2* __restrict__ wqh, __half2* __restrict__ wkh, __half2* __restrict__ wvh,
    float* __restrict__ cosT, float* __restrict__ sinT)
{
    int b = blockIdx.x, tid = threadIdx.x;
    if (b < 5632) {
        const float4* s; __half2* d; int i8;
        if (b < 4096) { s = x; d = xh; i8 = b * 256 + tid; }
        else {
            int wi = b - 4096;
            int w = wi >> 9, o = wi & 511;
            s = (w == 0) ? Wq : ((w == 1) ? Wk : Wv);
            d = (w == 0) ? wqh : ((w == 1) ? wkh : wvh);
            i8 = o * 256 + tid;
        }
        float4 a = s[i8 * 2], c = s[i8 * 2 + 1];
        d[i8 * 4 + 0] = __floats2half2_rn(a.x, a.y);
        d[i8 * 4 + 1] = __floats2half2_rn(a.z, a.w);
        d[i8 * 4 + 2] = __floats2half2_rn(c.x, c.y);
        d[i8 * 4 + 3] = __floats2half2_rn(c.z, c.w);
    } else {
        int idx = (b - 5632) * 256 + tid;         // < HALF_D*TT
        int pair = idx >> 11;                      // constant within block
        __shared__ double sh_theta;
        if (tid == 0)
            sh_theta = exp(-2.0 * (double)pair / (double)DD * 9.210340371976184);
        __syncthreads();
        float theta = (float)sh_theta;
        int t = idx & (TT - 1);
        float ang = (float)t * theta;              // fp32, matches reference
        double xx = (double)ang;
        double k = floor(xx * 0.15915494309189535);
        float r = (float)(xx - k * 6.283185307179586);
        cosT[idx] = cosf(r);
        sinT[idx] = sinf(r);
    }
}

// ---------------------------------------------------------------------------
// FP16 MMA GEMM, NT (R14 structure, unchanged mainloop):
// C[M,N] = A[M,K]*B[N,K]^T, 128x128 tile, BK=64, 3-stage cp.async, occ=2.
// Block-row order REVERSED (by = gridDim.y-1-blockIdx.y) so heavy causal
// rows schedule first (no-op for uniform qkv mode).
// ---------------------------------------------------------------------------
__global__ __launch_bounds__(256, 2) void mma_nt(
    const __half* __restrict__ A,
    const __half* __restrict__ B0, const __half* __restrict__ B1,
    const __half* __restrict__ B2,
    __half* __restrict__ C0, __half* __restrict__ C1, __half* __restrict__ C2,
    int K, int lda, int ldb, int ldc,
    long long sA, long long sB, long long sC,
    int qkv,
    const float* __restrict__ cosT, const float* __restrict__ sinT)
{
    int bz = blockIdx.z;
    int by = (int)gridDim.y - 1 - (int)blockIdx.y;   // heavy rows first
    const __half* Ap = A;
    const __half* Bp; __half* Cp; int rope;
    if (qkv) {
        Bp = (bz == 0) ? B0 : ((bz == 1) ? B1 : B2);
        Cp = (bz == 0) ? C0 : ((bz == 1) ? C1 : C2);
        rope = (bz < 2) ? 1 : 0;
    } else {
        if ((int)blockIdx.x > by + 1) return;
        Ap = A  + (long long)bz * sA;
        Bp = B0 + (long long)bz * sB;
        Cp = C0 + (long long)bz * sC;
        rope = 0;
    }
    const __half* Ab = Ap + (long long)by * 128 * lda;
    const __half* Bb = Bp + (long long)blockIdx.x * 128 * ldb;

    extern __shared__ char sm[];
    uint32_t su = smem_u32(sm);

    int tid = threadIdx.x, lane = tid & 31, warp = tid >> 5;
    int wy = warp >> 2, wx = warp & 3;
    int grp = lane >> 2, l4 = lane & 3;
    int arow_l = lane & 15, ak_h = lane >> 4;
    int brow_l = lane & 7,  bk_h = (lane >> 3) & 1;

    float acc[4][4][4];
#pragma unroll
    for (int mt = 0; mt < 4; mt++)
#pragma unroll
        for (int nt = 0; nt < 4; nt++)
#pragma unroll
            for (int j = 0; j < 4; j++) acc[mt][nt][j] = 0.f;

    int ntiles = K >> 6;   // BK=64 halfs

    // stage: A 128x128B (16KB) + B 128x128B (16KB) = 32KB; 3 stages
#define NT_LOAD(stage, k0)                                                    \
    {                                                                         \
        uint32_t sa_ = su + (stage) * 32768;                                  \
        _Pragma("unroll")                                                     \
        for (int l = 0; l < 4; l++) {                                         \
            int v = tid + l * 256;                                            \
            int r = v >> 3, c4 = v & 7;                                       \
            uint32_t off = (uint32_t)(r * 128 + ((c4 ^ (r & 7)) << 4));       \
            cp16(sa_ + off,         Ab + (long long)r * lda + (k0) + c4 * 8); \
            cp16(sa_ + 16384 + off, Bb + (long long)r * ldb + (k0) + c4 * 8); \
        }                                                                     \
    }

    NT_LOAD(0, 0);  cp_commit();
    NT_LOAD(1, 64); cp_commit();

    int rs = 0;
    for (int t = 0; t < ntiles; t++) {
        cp_wait1();
        __syncthreads();
        uint32_t sa = su + rs * 32768;
        uint32_t sb = sa + 16384;
#pragma unroll
        for (int ks = 0; ks < 4; ks++) {       // k16 per step
            int kc = ks * 2;                   // 16B chunk index
            uint32_t afr[4][4], bfr[4][2];
#pragma unroll
            for (int mt = 0; mt < 4; mt++) {
                int row = wy * 64 + mt * 16 + arow_l;
                int ch  = (kc + ak_h) ^ (row & 7);
                ldsm_x4(afr[mt], sa + (uint32_t)(row * 128 + (ch << 4)));
            }
#pragma unroll
            for (int nt = 0; nt < 4; nt++) {
                int row = wx * 32 + nt * 8 + brow_l;
                int ch  = (kc + bk_h) ^ (row & 7);
                ldsm_x2(bfr[nt], sb + (uint32_t)(row * 128 + (ch << 4)));
            }
#pragma unroll
            for (int mt = 0; mt < 4; mt++)
#pragma unroll
                for (int nt = 0; nt < 4; nt++)
                    mma_f16(acc[mt][nt], afr[mt], bfr[nt]);
        }
        int tn = t + 2;
        if (tn < ntiles) {
            int ws = rs + 2; if (ws >= 3) ws -= 3;
            NT_LOAD(ws, tn * 64);
        }
        cp_commit();
        rs++; if (rs == 3) rs = 0;
    }
#undef NT_LOAD

    int row0 = by * 128 + wy * 64;
    int col0 = blockIdx.x * 128 + wx * 32;
#pragma unroll
    for (int mt = 0; mt < 4; mt++) {
        int r1 = row0 + mt * 16 + grp;
        int r2 = r1 + 8;
#pragma unroll
        for (int nt = 0; nt < 4; nt++) {
            int cc = col0 + nt * 8 + l4 * 2;
            float e0 = acc[mt][nt][0], o0 = acc[mt][nt][1];
            float e1 = acc[mt][nt][2], o1 = acc[mt][nt][3];
            if (rope) {
                int p  = cc >> 1;
                int t1 = r1 & (TT - 1), t2 = r2 & (TT - 1);
                float c1v = cosT[(size_t)p * TT + t1], s1v = sinT[(size_t)p * TT + t1];
                float c2v = cosT[(size_t)p * TT + t2], s2v = sinT[(size_t)p * TT + t2];
                float ne0 = e0 * c1v - o0 * s1v, no0 = e0 * s1v + o0 * c1v;
                float ne1 = e1 * c2v - o1 * s2v, no1 = e1 * s2v + o1 * c2v;
                e0 = ne0; o0 = no0; e1 = ne1; o1 = no1;
            }
            *(__half2*)(Cp + (long long)r1 * ldc + cc) = __floats2half2_rn(e0, o0);
            *(__half2*)(Cp + (long long)r2 * ldc + cc) = __floats2half2_rn(e1, o1);
        }
    }
}

// ---------------------------------------------------------------------------
// FP16 MMA GEMM, NN (R14 structure, unchanged mainloop):
// C[M,N] = A[M,K]*B[K,N], fp32 out. B frags via ldmatrix.x2.trans on
// [k][136]-half tile. K bounded per q-block. Block-row order reversed.
// ---------------------------------------------------------------------------
__global__ __launch_bounds__(256, 2) void mma_nn(
    const __half* __restrict__ A, const __half* __restrict__ B,
    float* __restrict__ C,
    int K, int lda, int ldb, int ldc,
    long long sA, long long sB, long long sC)
{
    int by = (int)gridDim.y - 1 - (int)blockIdx.y;   // heavy rows first
    const __half* Ab = A + (long long)blockIdx.z * sA + (long long)by * 128 * lda;
    const __half* Bb = B + (long long)blockIdx.z * sB + (long long)blockIdx.x * 128;
    float*        Cb = C + (long long)blockIdx.z * sC;

    int Kend = min((by + 2) * 128, K);
    int ntiles = Kend >> 6;

    extern __shared__ char sm[];
    uint32_t su = smem_u32(sm);

    int tid = threadIdx.x, lane = tid & 31, warp = tid >> 5;
    int wy = warp >> 2, wx = warp & 3;
    int grp = lane >> 2, l4 = lane & 3;
    int arow_l = lane & 15, ak_h = lane >> 4;
    int lan16 = lane & 15;

    float acc[4][4][4];
#pragma unroll
    for (int mt = 0; mt < 4; mt++)
#pragma unroll
        for (int nt = 0; nt < 4; nt++)
#pragma unroll
            for (int j = 0; j < 4; j++) acc[mt][nt][j] = 0.f;

    // stage: A 16384B + B 64*272B = 17408B -> 33792B; 3 stages
#define NN_LOAD(stage, k0)                                                      \
    {                                                                           \
        uint32_t sa_ = su + (stage) * 33792;                                    \
        _Pragma("unroll")                                                       \
        for (int l = 0; l < 4; l++) {                                           \
            int v = tid + l * 256;                                              \
            int r = v >> 3, c4 = v & 7;                                         \
            uint32_t off = (uint32_t)(r * 128 + ((c4 ^ (r & 7)) << 4));         \
            cp16(sa_ + off, Ab + (long long)r * lda + (k0) + c4 * 8);           \
            int br = v >> 4, bc = (v & 15) * 8;                                 \
            cp16(sa_ + 16384 + (uint32_t)(br * 272 + bc * 2),                   \
                 Bb + (long long)((k0) + br) * ldb + bc);                       \
        }                                                                       \
    }

    NN_LOAD(0, 0);  cp_commit();
    NN_LOAD(1, 64); cp_commit();

    int rs = 0;
    for (int t = 0; t < ntiles; t++) {
        cp_wait1();
        __syncthreads();
        uint32_t sa = su + rs * 33792;
        uint32_t sb = sa + 16384;
#pragma unroll
        for (int ks = 0; ks < 4; ks++) {
            int kc = ks * 2;
            int kb = ks * 16;                  // k offset in halfs
            uint32_t afr[4][4], bfr[4][2];
#pragma unroll
            for (int mt = 0; mt < 4; mt++) {
                int row = wy * 64 + mt * 16 + arow_l;
                int ch  = (kc + ak_h) ^ (row & 7);
                ldsm_x4(afr[mt], sa + (uint32_t)(row * 128 + (ch << 4)));
            }
#pragma unroll
            for (int nt = 0; nt < 4; nt++) {
                int n0 = wx * 32 + nt * 8;
                int krow = kb + lan16;
                ldsm_x2_t(bfr[nt], sb + (uint32_t)(krow * 272 + n0 * 2));
            }
#pragma unroll
            for (int mt = 0; mt < 4; mt++)
#pragma unroll
                for (int nt = 0; nt < 4; nt++)
                    mma_f16(acc[mt][nt], afr[mt], bfr[nt]);
        }
        int tn = t + 2;
        if (tn < ntiles) {
            int ws = rs + 2; if (ws >= 3) ws -= 3;
            NN_LOAD(ws, tn * 64);
        }
        cp_commit();
        rs++; if (rs == 3) rs = 0;
    }
#undef NN_LOAD

    int row0 = by * 128 + wy * 64;
    int col0 = blockIdx.x * 128 + wx * 32;
#pragma unroll
    for (int mt = 0; mt < 4; mt++) {
        int r1 = row0 + mt * 16 + grp;
        int r2 = r1 + 8;
#pragma unroll
        for (int nt = 0; nt < 4; nt++) {
            int cc = col0 + nt * 8 + l4 * 2;
            *(float2*)(Cb + (long long)r1 * ldc + cc) =
                make_float2(acc[mt][nt][0], acc[mt][nt][1]);
            *(float2*)(Cb + (long long)r2 * ldc + cc) =
                make_float2(acc[mt][nt][2], acc[mt][nt][3]);
        }
    }
}

// ---------------------------------------------------------------------------
// Row softmax on __half scores. 8 halfs/thread covers a 2048 row.
// Valid prefix n=q+2, scale 1/32, fp32 math, fp16 probs. Zero-fill to bound.
// ---------------------------------------------------------------------------
__global__ __launch_bounds__(256) void softmax_rows(__half* __restrict__ S)
{
    int row = blockIdx.x;                 // b*T + q
    int q   = row & (TT - 1);
    __half* s = S + (size_t)row * TT;
    int n    = min(q + 2, TT);
    int zend = min((((q >> 7) + 2) << 7), TT);
    int nv8  = (n + 7) >> 3;

    int tid = threadIdx.x;
    uint4* s8 = (uint4*)s;

    float v[8];
    float m = -1e30f;
    if (tid < nv8) {
        uint4 u = s8[tid];
        __half2* h = (__half2*)&u;
        int base = tid * 8;
#pragma unroll
        for (int k = 0; k < 4; k++) {
            float2 f = __half22float2(h[k]);
            v[k*2]   = (base + k*2     < n) ? f.x : -1e30f;
            v[k*2+1] = (base + k*2 + 1 < n) ? f.y : -1e30f;
        }
#pragma unroll
        for (int k = 0; k < 8; k++) m = fmaxf(m, v[k]);
    } else {
#pragma unroll
        for (int k = 0; k < 8; k++) v[k] = -1e30f;
    }

    __shared__ float red[8];
#pragma unroll
    for (int o = 16; o; o >>= 1) m = fmaxf(m, __shfl_xor_sync(0xffffffffu, m, o));
    if ((tid & 31) == 0) red[tid >> 5] = m;
    __syncthreads();
    m = red[0];
#pragma unroll
    for (int w = 1; w < 8; w++) m = fmaxf(m, red[w]);
    __syncthreads();

    float sum = 0.f;
#pragma unroll
    for (int k = 0; k < 8; k++) {
        v[k] = fexp((v[k] - m) * 0.03125f);
        sum += v[k];
    }
    if (tid >= nv8) sum = 0.f;
#pragma unroll
    for (int o = 16; o; o >>= 1) sum += __shfl_xor_sync(0xffffffffu, sum, o);
    if ((tid & 31) == 0) red[tid >> 5] = sum;
    __syncthreads();
    float tot = 0.f;
#pragma unroll
    for (int w = 0; w < 8; w++) tot += red[w];
    float inv = 1.0f / tot;

    if (tid < nv8) {
        uint4 u;
        __half2* h = (__half2*)&u;
#pragma unroll
        for (int k = 0; k < 4; k++)
            h[k] = __floats2half2_rn(v[k*2] * inv, v[k*2+1] * inv);
        s8[tid] = u;
    }
    for (int j = nv8 * 8 + tid; j < zend; j += 256) s[j] = __ushort_as_half(0);
}

// ---------------------------------------------------------------------------
// Launch: setup -> fused QKV (rope) -> scores -> softmax -> PV
// ---------------------------------------------------------------------------
extern "C" void kernel_launch(void* const* d_in, const int* in_sizes, int n_in,
                              void* d_out, int out_size)
{
    const float* x  = (const float*)d_in[0];
    const float* Wq = (const float*)d_in[1];
    const float* Wk = (const float*)d_in[2];
    const float* Wv = (const float*)d_in[3];
    float* out = (float*)d_out;

    float *Qf, *Kf, *Vf, *S, *cT, *sT;
    cudaGetSymbolAddress((void**)&Qf, g_Q);
    cudaGetSymbolAddress((void**)&Kf, g_K);
    cudaGetSymbolAddress((void**)&Vf, g_V);
    cudaGetSymbolAddress((void**)&S,  g_S);
    cudaGetSymbolAddress((void**)&cT, g_cosT);
    cudaGetSymbolAddress((void**)&sT, g_sinT);

    __half* Qh = (__half*)Qf;
    __half* Kh = (__half*)Kf;
    __half* Vh = (__half*)Vf;
    __half* Sh = (__half*)S;                                  // 16M halfs
    __half* xh  = (__half*)(S + (size_t)8  * 1024 * 1024);    // 8M halfs
    __half* wqh = (__half*)(S + (size_t)12 * 1024 * 1024);    // 1M halfs each
    __half* wkh = wqh + 1024 * 1024;
    __half* wvh = wkh + 1024 * 1024;

    cudaFuncSetAttribute(mma_nt, cudaFuncAttributeMaxDynamicSharedMemorySize, 98304);
    cudaFuncSetAttribute(mma_nn, cudaFuncAttributeMaxDynamicSharedMemorySize, 101376);

    dim3 blk(256);
    const long long TD  = (long long)TT * DD;   // in halfs
    const long long TT2 = (long long)TT * TT;

    // Setup: fp16-round x/W* (5632 blocks) + rope table (4096 blocks)
    setup_kernel<<<5632 + 4096, blk>>>(
        (const float4*)x, (const float4*)Wq, (const float4*)Wk, (const float4*)Wv,
        (__half2*)xh, (__half2*)wqh, (__half2*)wkh, (__half2*)wvh, cT, sT);

    // Fused QKV: z=0/1/2 -> Q/K/V (half); rope fused for Q,K
    mma_nt<<<dim3(DD / 128, (BATCH * TT) / 128, 3), blk, 98304>>>(
        xh, wqh, wkh, wvh, Qh, Kh, Vh,
        DD, DD, DD, DD, 0, 0, 0, 1, cT, sT);

    // Scores: Sh[b] = Qr[b]*Kr[b]^T (half out; causal block skip)
    mma_nt<<<dim3(TT / 128, TT / 128, BATCH), blk, 98304>>>(
        Qh, Kh, nullptr, nullptr, Sh, nullptr, nullptr,
        DD, DD, DD, TT, TD, TD, TT2, 0, cT, sT);

    // Softmax (scale 1/32, causal mask, fp16 probs, zero-fill)
    softmax_rows<<<BATCH * TT, blk>>>(Sh);

    // Out: O[b] = P[b]*V[b] (K bounded per q-block; fp32 out)
    mma_nn<<<dim3(DD / 128, TT / 128, BATCH), blk, 101376>>>(
        Sh, Vh, out, TT, TT, DD, DD, TT2, TD, TD);
}